// round 5
// baseline (speedup 1.0000x reference)
#include <cuda_runtime.h>
#include <math.h>

// MySimpleRNN: h_final[B,NH] from 64-step tanh RNN.
//   h_t = tanh(x_t @ wx + h_{t-1} @ wh + b),  h_0 = 0
// Fused per-step GEMM: M=B=4096, N=NH=512, K=NH(=512, recurrent) + NF(=128, input proj).
// 64 sequential kernel launches in the captured graph; ping-pong H in __device__ scratch.

#define NF 128
#define NH 512
#define TT 64
#define BMAX 4096

#define BM 128
#define BN 128
#define BK 8
#define TM 8
#define TN 8
#define NTHREADS 256

// Ping-pong hidden-state scratch (16 MB). Overwritten every replay -> deterministic.
__device__ float g_h[2][(size_t)BMAX * NH];

// One k-tile: load A (transposed into As) + B, sync, 8x (8x8 FMA), sync.
#define GEMM_KTILE(APTR_K, BPTR_K)                                              \
    {                                                                           \
        float4 av = *(const float4*)(APTR_K);                                   \
        As[acol + 0][arow] = av.x;                                              \
        As[acol + 1][arow] = av.y;                                              \
        As[acol + 2][arow] = av.z;                                              \
        As[acol + 3][arow] = av.w;                                              \
        *(float4*)(&Bs[brow][bcol]) = *(const float4*)(BPTR_K);                 \
        __syncthreads();                                                        \
        _Pragma("unroll")                                                       \
        for (int k = 0; k < BK; ++k) {                                          \
            float4 a0 = *(const float4*)(&As[k][ty * TM]);                      \
            float4 a1 = *(const float4*)(&As[k][ty * TM + 4]);                  \
            float4 b0 = *(const float4*)(&Bs[k][tx * TN]);                      \
            float4 b1 = *(const float4*)(&Bs[k][tx * TN + 4]);                  \
            float ar[TM] = {a0.x, a0.y, a0.z, a0.w, a1.x, a1.y, a1.z, a1.w};    \
            float br[TN] = {b0.x, b0.y, b0.z, b0.w, b1.x, b1.y, b1.z, b1.w};    \
            _Pragma("unroll")                                                   \
            for (int i = 0; i < TM; ++i) {                                      \
                _Pragma("unroll")                                               \
                for (int j = 0; j < TN; ++j) {                                  \
                    acc[i][j] += ar[i] * br[j];                                 \
                }                                                               \
            }                                                                   \
        }                                                                       \
        __syncthreads();                                                        \
    }

__global__ __launch_bounds__(NTHREADS)
void rnn_step_kernel(const float* __restrict__ x,    // [B, TT, NF]
                     const float* __restrict__ wx,   // [NF, NH]
                     const float* __restrict__ wh,   // [NH, NH]
                     const float* __restrict__ bias, // [NH]
                     float* __restrict__ dout,       // [B, NH] (used at t == TT-1)
                     int t)
{
    __shared__ float As[BK][BM];
    __shared__ float Bs[BK][BN];

    const int m0 = blockIdx.y * BM;
    const int n0 = blockIdx.x * BN;
    const int tid = threadIdx.x;
    const int tx = tid & 15;   // 0..15 -> column micro-tile
    const int ty = tid >> 4;   // 0..15 -> row micro-tile

    // A-tile loader: 128 rows x 8 k, one float4 per thread.
    const int arow = tid >> 1;         // 0..127
    const int acol = (tid & 1) << 2;   // 0 or 4
    // B-tile loader: 8 k x 128 cols, one float4 per thread.
    const int brow = tid >> 5;         // 0..7
    const int bcol = (tid & 31) << 2;  // 0..124

    float acc[TM][TN];
#pragma unroll
    for (int i = 0; i < TM; ++i)
#pragma unroll
        for (int j = 0; j < TN; ++j)
            acc[i][j] = 0.0f;

    // ---- Segment 1: h_{t-1} @ wh  (K = NH), skipped at t == 0 (h_0 = 0) ----
    if (t > 0) {
        const float* hin = g_h[(t + 1) & 1];
        const float* aBase = hin + (m0 + arow) * NH + acol;
        const float* bBase = wh + brow * NH + n0 + bcol;
#pragma unroll 4
        for (int k0 = 0; k0 < NH; k0 += BK) {
            GEMM_KTILE(aBase + k0, bBase + (size_t)k0 * NH);
        }
    }

    // ---- Segment 2: x_t @ wx  (K = NF) ----
    {
        const float* aBase = x + (size_t)(m0 + arow) * (TT * NF) + t * NF + acol;
        const float* bBase = wx + brow * NH + n0 + bcol;
#pragma unroll 4
        for (int k0 = 0; k0 < NF; k0 += BK) {
            GEMM_KTILE(aBase + k0, bBase + (size_t)k0 * NH);
        }
    }

    // ---- Epilogue: h' = tanh(acc + b) ----
    float* hout = (t == TT - 1) ? dout : g_h[t & 1];
    float bv[TN];
#pragma unroll
    for (int j = 0; j < TN; ++j)
        bv[j] = bias[n0 + tx * TN + j];

#pragma unroll
    for (int i = 0; i < TM; ++i) {
        float* op = hout + (size_t)(m0 + ty * TM + i) * NH + n0 + tx * TN;
        float4 o0, o1;
        o0.x = tanhf(acc[i][0] + bv[0]);
        o0.y = tanhf(acc[i][1] + bv[1]);
        o0.z = tanhf(acc[i][2] + bv[2]);
        o0.w = tanhf(acc[i][3] + bv[3]);
        o1.x = tanhf(acc[i][4] + bv[4]);
        o1.y = tanhf(acc[i][5] + bv[5]);
        o1.z = tanhf(acc[i][6] + bv[6]);
        o1.w = tanhf(acc[i][7] + bv[7]);
        *(float4*)(op)     = o0;
        *(float4*)(op + 4) = o1;
    }
}

extern "C" void kernel_launch(void* const* d_in, const int* in_sizes, int n_in,
                              void* d_out, int out_size)
{
    const float* x  = (const float*)d_in[0];  // [B, 64, 128]
    const float* wx = (const float*)d_in[1];  // [128, 512]
    const float* wh = (const float*)d_in[2];  // [512, 512]
    const float* b  = (const float*)d_in[3];  // [1, 512]
    float* out = (float*)d_out;               // [B, 512]

    const int B = in_sizes[0] / (TT * NF);    // 4096
    dim3 grid(NH / BN, B / BM);               // (4, 32) = 128 blocks

    for (int t = 0; t < TT; ++t) {
        rnn_step_kernel<<<grid, NTHREADS>>>(x, wx, wh, b, out, t);
    }
}

// round 8
// speedup vs baseline: 3.0031x; 3.0031x over previous
#include <cuda_runtime.h>
#include <cuda_bf16.h>
#include <cstdint>
#include <math.h>

// MySimpleRNN: h_t = tanh(x_t@wx + h_{t-1}@wh + b), 64 steps, h_final[4096,512].
// Tensor-core path that compiles for compute_103 (no "a" features):
//   mma.sync.m16n8k16 bf16 + ldmatrix + cp.async double buffering.
// Split precision: A*B ~= Ahi*Bhi + Ahi*Blo + Alo*Bhi, fp32 accum (err ~2^-17/product).
// Per step: GEMM M=4096, N=512, K=512(recurrent)+128(input). 64 launches in graph.

#define NF 128
#define NH 512
#define TT 64
#define BMAX 4096

#define BM 128
#define BN 128
#define KC 64          // K per smem chunk
#define NTHREADS 256   // 8 warps: 4 (M) x 2 (N); warp tile 32x64

// ---------------- scratch (device globals; no allocation) ----------------
__device__ __align__(1024) __nv_bfloat16 g_hhi[2][(size_t)BMAX * NH];
__device__ __align__(1024) __nv_bfloat16 g_hlo[2][(size_t)BMAX * NH];
__device__ __align__(1024) __nv_bfloat16 g_xhi[TT][(size_t)BMAX * NF];
__device__ __align__(1024) __nv_bfloat16 g_xlo[TT][(size_t)BMAX * NF];
__device__ __align__(1024) __nv_bfloat16 g_wh_hi[NH * NH];   // [k][n], original layout
__device__ __align__(1024) __nv_bfloat16 g_wh_lo[NH * NH];
__device__ __align__(1024) __nv_bfloat16 g_wx_hi[NF * NH];   // [k][n]
__device__ __align__(1024) __nv_bfloat16 g_wx_lo[NF * NH];

// ---------------- helpers ----------------
__device__ __forceinline__ uint32_t smem_u32(const void* p) {
    uint32_t a;
    asm("{ .reg .u64 t; cvta.to.shared.u64 t, %1; cvt.u32.u64 %0, t; }" : "=r"(a) : "l"(p));
    return a;
}

__device__ __forceinline__ void ldsm_x4(uint32_t* r, uint32_t addr) {
    asm volatile("ldmatrix.sync.aligned.m8n8.x4.shared.b16 {%0,%1,%2,%3}, [%4];"
                 : "=r"(r[0]), "=r"(r[1]), "=r"(r[2]), "=r"(r[3]) : "r"(addr));
}
__device__ __forceinline__ void ldsm_x4_t(uint32_t* r, uint32_t addr) {
    asm volatile("ldmatrix.sync.aligned.m8n8.x4.trans.shared.b16 {%0,%1,%2,%3}, [%4];"
                 : "=r"(r[0]), "=r"(r[1]), "=r"(r[2]), "=r"(r[3]) : "r"(addr));
}
__device__ __forceinline__ void mma16816(float* d, const uint32_t* a, const uint32_t* b) {
    asm volatile(
        "mma.sync.aligned.m16n8k16.row.col.f32.bf16.bf16.f32 "
        "{%0,%1,%2,%3}, {%4,%5,%6,%7}, {%8,%9}, {%0,%1,%2,%3};"
        : "+f"(d[0]), "+f"(d[1]), "+f"(d[2]), "+f"(d[3])
        : "r"(a[0]), "r"(a[1]), "r"(a[2]), "r"(a[3]), "r"(b[0]), "r"(b[1]));
}
__device__ __forceinline__ void cp_async16(uint32_t dst, const void* src) {
    asm volatile("cp.async.cg.shared.global [%0], [%1], 16;" :: "r"(dst), "l"(src) : "memory");
}
#define CP_COMMIT() asm volatile("cp.async.commit_group;" ::: "memory")
#define CP_WAIT(n)  asm volatile("cp.async.wait_group %0;" :: "n"(n) : "memory")

__device__ __forceinline__ uint32_t pack_bf16x2(float a, float b) {
    __nv_bfloat16 ha = __float2bfloat16(a);
    __nv_bfloat16 hb = __float2bfloat16(b);
    return ((uint32_t)__bfloat16_as_ushort(hb) << 16) | (uint32_t)__bfloat16_as_ushort(ha);
}

// ---------------- precompute ----------------
__global__ void prep_weights(const float* __restrict__ wx, const float* __restrict__ wh) {
    int idx = blockIdx.x * blockDim.x + threadIdx.x;
    if (idx < NH * NH) {
        float v = wh[idx];
        __nv_bfloat16 hi = __float2bfloat16(v);
        g_wh_hi[idx] = hi;
        g_wh_lo[idx] = __float2bfloat16(v - __bfloat162float(hi));
    }
    if (idx < NF * NH) {
        float v = wx[idx];
        __nv_bfloat16 hi = __float2bfloat16(v);
        g_wx_hi[idx] = hi;
        g_wx_lo[idx] = __float2bfloat16(v - __bfloat162float(hi));
    }
}

__global__ void prep_x(const float* __restrict__ x, int B) {
    size_t idx = (size_t)blockIdx.x * blockDim.x + threadIdx.x;
    if (idx < (size_t)B * TT * NF) {
        int f = (int)(idx % NF);
        size_t r = idx / NF;
        int t = (int)(r % TT);
        size_t b = r / TT;
        float v = x[idx];
        __nv_bfloat16 hi = __float2bfloat16(v);
        g_xhi[t][b * NF + f] = hi;
        g_xlo[t][b * NF + f] = __float2bfloat16(v - __bfloat162float(hi));
    }
}

// ---------------- step kernel ----------------
// smem per buffer (64KB): Ahi[128][64] | Alo | Bhi[64][128] | Blo   (bf16, swizzled)
// A row: 128B = 8 chunks of 16B, chunk ^= (row&7). B row: 256B = 16 chunks, chunk ^= (krow&7).
#define BUF_BYTES 65536
#define SMEM_BYTES (2 * BUF_BYTES)

__global__ __launch_bounds__(NTHREADS, 1)
void rnn_step_mma(const float* __restrict__ bias, float* __restrict__ dout, int t)
{
    extern __shared__ __align__(1024) char smem[];
    const uint32_t sbase = smem_u32(smem);

    const int tid = threadIdx.x;
    const int wid = tid >> 5;
    const int lid = tid & 31;
    const int wm = wid & 3;        // warp row: 32 M each
    const int wn = wid >> 2;       // warp col: 64 N each
    const int m0 = blockIdx.y * BM;
    const int n0 = blockIdx.x * BN;

    const int nrec = (t > 0) ? (NH / KC) : 0;   // 8
    const int nchunks = nrec + NF / KC;          // +2
    const int src = (t + 1) & 1;

    const __nv_bfloat16* hAhi = g_hhi[src] + (size_t)m0 * NH;
    const __nv_bfloat16* hAlo = g_hlo[src] + (size_t)m0 * NH;
    const __nv_bfloat16* xAhi = g_xhi[t] + (size_t)m0 * NF;
    const __nv_bfloat16* xAlo = g_xlo[t] + (size_t)m0 * NF;

    float acc[2][8][4];
#pragma unroll
    for (int i = 0; i < 2; ++i)
#pragma unroll
        for (int j = 0; j < 8; ++j)
#pragma unroll
            for (int q = 0; q < 4; ++q) acc[i][j][q] = 0.0f;

    // ---- chunk loader: 16 cp.async/thread (A hi/lo: 8, B hi/lo: 8) ----
    auto load_chunk = [&](int c, int buf) {
        const __nv_bfloat16 *gAh, *gAl, *gBh, *gBl;
        int lda, kbase;
        if (c < nrec) { gAh = hAhi; gAl = hAlo; gBh = g_wh_hi; gBl = g_wh_lo; lda = NH; kbase = c * KC; }
        else          { gAh = xAhi; gAl = xAlo; gBh = g_wx_hi; gBl = g_wx_lo; lda = NF; kbase = (c - nrec) * KC; }
        const uint32_t sb = sbase + (uint32_t)buf * BUF_BYTES;
        // A tiles: 1024 segs each (row 0..127, chunk 0..7) -> 4/thread per tile
#pragma unroll
        for (int j = 0; j < 4; ++j) {
            int seg = j * 256 + tid;
            uint32_t row = (uint32_t)(seg >> 3);
            uint32_t ch = (uint32_t)(seg & 7);
            uint32_t off = row * 128u + ((ch ^ (row & 7u)) << 4);
            const __nv_bfloat16* sA = gAh + (size_t)row * lda + kbase + ch * 8;
            cp_async16(sb + off, sA);
            cp_async16(sb + 16384u + off, gAl + (size_t)row * lda + kbase + ch * 8);
        }
        // B tiles: 1024 segs each (krow 0..63, chunk 0..15)
#pragma unroll
        for (int j = 0; j < 4; ++j) {
            int seg = j * 256 + tid;
            uint32_t kr = (uint32_t)(seg >> 4);
            uint32_t ch = (uint32_t)(seg & 15);
            uint32_t off = kr * 256u + ((ch ^ (kr & 7u)) << 4);
            const __nv_bfloat16* sB = gBh + (size_t)(kbase + kr) * NH + n0 + ch * 8;
            cp_async16(sb + 32768u + off, sB);
            cp_async16(sb + 49152u + off, gBl + (size_t)(kbase + kr) * NH + n0 + ch * 8);
        }
        CP_COMMIT();
    };

    load_chunk(0, 0);
    load_chunk(1, 1);

    for (int i = 0; i < nchunks; ++i) {
        const int buf = i & 1;
        if (i + 1 < nchunks) CP_WAIT(1); else CP_WAIT(0);
        __syncthreads();

        const uint32_t sb = sbase + (uint32_t)buf * BUF_BYTES;
        const uint32_t aHi = sb, aLo = sb + 16384u, bHi = sb + 32768u, bLo = sb + 49152u;

#pragma unroll
        for (int kk = 0; kk < KC / 16; ++kk) {
            const int k0 = kk * 16;
            uint32_t ah[2][4], al[2][4];
#pragma unroll
            for (int mt = 0; mt < 2; ++mt) {
                uint32_t row = (uint32_t)(wm * 32 + mt * 16 + ((lid >> 3) & 1) * 8 + (lid & 7));
                uint32_t kc = (uint32_t)((k0 >> 3) + (lid >> 4));
                uint32_t off = row * 128u + ((kc ^ (row & 7u)) << 4);
                ldsm_x4(ah[mt], aHi + off);
                ldsm_x4(al[mt], aLo + off);
            }
            uint32_t bh[8][2], bl[8][2];
#pragma unroll
            for (int np = 0; np < 4; ++np) {
                int g = lid >> 3;
                uint32_t kr = (uint32_t)(k0 + (g & 1) * 8 + (lid & 7));
                uint32_t nc = (uint32_t)(((wn * 64 + np * 16) >> 3) + (g >> 1));
                uint32_t off = kr * 256u + ((nc ^ (kr & 7u)) << 4);
                uint32_t r[4];
                ldsm_x4_t(r, bHi + off);
                bh[np * 2][0] = r[0]; bh[np * 2][1] = r[1];
                bh[np * 2 + 1][0] = r[2]; bh[np * 2 + 1][1] = r[3];
                ldsm_x4_t(r, bLo + off);
                bl[np * 2][0] = r[0]; bl[np * 2][1] = r[1];
                bl[np * 2 + 1][0] = r[2]; bl[np * 2 + 1][1] = r[3];
            }
#pragma unroll
            for (int mt = 0; mt < 2; ++mt)
#pragma unroll
                for (int nt = 0; nt < 8; ++nt) {
                    mma16816(acc[mt][nt], ah[mt], bh[nt]);   // hi*hi
                    mma16816(acc[mt][nt], ah[mt], bl[nt]);   // hi*lo
                    mma16816(acc[mt][nt], al[mt], bh[nt]);   // lo*hi
                }
        }

        __syncthreads();
        if (i + 2 < nchunks) load_chunk(i + 2, buf);
    }

    // ---- epilogue: tanh(acc + bias); split to bf16 hi/lo, or fp32 out at t=63 ----
    const bool last = (t == TT - 1);
    const int dst = t & 1;
    const int gq = lid >> 2;       // 0..7
    const int tq = lid & 3;        // 0..3
#pragma unroll
    for (int mt = 0; mt < 2; ++mt) {
#pragma unroll
        for (int nt = 0; nt < 8; ++nt) {
            const int col = n0 + wn * 64 + nt * 8 + tq * 2;
            const float2 bv = *(const float2*)(bias + col);
            const int r0 = m0 + wm * 32 + mt * 16 + gq;
            const int r1 = r0 + 8;
            float v00 = tanhf(acc[mt][nt][0] + bv.x);
            float v01 = tanhf(acc[mt][nt][1] + bv.y);
            float v10 = tanhf(acc[mt][nt][2] + bv.x);
            float v11 = tanhf(acc[mt][nt][3] + bv.y);
            if (last) {
                *(float2*)(dout + (size_t)r0 * NH + col) = make_float2(v00, v01);
                *(float2*)(dout + (size_t)r1 * NH + col) = make_float2(v10, v11);
            } else {
                __nv_bfloat16 h00 = __float2bfloat16(v00);
                __nv_bfloat16 h01 = __float2bfloat16(v01);
                __nv_bfloat16 h10 = __float2bfloat16(v10);
                __nv_bfloat16 h11 = __float2bfloat16(v11);
                *(uint32_t*)&g_hhi[dst][(size_t)r0 * NH + col] =
                    ((uint32_t)__bfloat16_as_ushort(h01) << 16) | (uint32_t)__bfloat16_as_ushort(h00);
                *(uint32_t*)&g_hhi[dst][(size_t)r1 * NH + col] =
                    ((uint32_t)__bfloat16_as_ushort(h11) << 16) | (uint32_t)__bfloat16_as_ushort(h10);
                *(uint32_t*)&g_hlo[dst][(size_t)r0 * NH + col] =
                    pack_bf16x2(v00 - __bfloat162float(h00), v01 - __bfloat162float(h01));
                *(uint32_t*)&g_hlo[dst][(size_t)r1 * NH + col] =
                    pack_bf16x2(v10 - __bfloat162float(h10), v11 - __bfloat162float(h11));
            }
        }
    }
}

// ---------------- launch ----------------
extern "C" void kernel_launch(void* const* d_in, const int* in_sizes, int n_in,
                              void* d_out, int out_size)
{
    const float* x  = (const float*)d_in[0];  // [B, 64, 128]
    const float* wx = (const float*)d_in[1];  // [128, 512]
    const float* wh = (const float*)d_in[2];  // [512, 512]
    const float* b  = (const float*)d_in[3];  // [1, 512]
    float* out = (float*)d_out;               // [B, 512]

    const int B = in_sizes[0] / (TT * NF);    // 4096

    cudaFuncSetAttribute(rnn_step_mma, cudaFuncAttributeMaxDynamicSharedMemorySize, SMEM_BYTES);

    prep_weights<<<(NH * NH + 255) / 256, 256>>>(wx, wh);
    {
        size_t n = (size_t)B * TT * NF;
        prep_x<<<(unsigned)((n + 255) / 256), 256>>>(x, B);
    }

    dim3 grid(NH / BN, B / BM);               // (4, 32) = 128 CTAs
    for (int t = 0; t < TT; ++t) {
        rnn_step_mma<<<grid, NTHREADS, SMEM_BYTES>>>(b, out, t);
    }
}